// round 2
// baseline (speedup 1.0000x reference)
#include <cuda_runtime.h>
#include <cuda_bf16.h>
#include <cstdint>

#define NN 4096
#define FF 512
#define DD 128
#define HH 8

// ---------------- scratch (static device globals; no allocs) ----------------
__device__ __nv_bfloat16 g_featb[NN * FF];          // 4 MB
__device__ __nv_bfloat16 g_Wb[HH * FF * DD];        // 1 MB
__device__ __nv_bfloat16 g_Whb[HH * NN * DD];       // 8 MB
__device__ float g_s1[HH * NN];
__device__ float g_s2[HH * NN];
__device__ unsigned g_adjbits[NN * (NN / 32)];      // 2 MB
__device__ float g_accum[NN * DD];                  // 2 MB (sum over heads of elu(h'))

// ---------------- helpers ----------------
__device__ __forceinline__ unsigned pack_bf16x2(float lo, float hi) {
    unsigned r;
    asm("cvt.rn.bf16x2.f32 %0, %1, %2;" : "=r"(r) : "f"(hi), "f"(lo));
    return r;
}

__device__ __forceinline__ unsigned smem_u32(const void* p) {
    return (unsigned)__cvta_generic_to_shared(p);
}

__device__ __forceinline__ void ldsm_x4(unsigned addr, unsigned& r0, unsigned& r1,
                                        unsigned& r2, unsigned& r3) {
    asm volatile("ldmatrix.sync.aligned.m8n8.x4.shared.b16 {%0,%1,%2,%3}, [%4];"
                 : "=r"(r0), "=r"(r1), "=r"(r2), "=r"(r3) : "r"(addr));
}

__device__ __forceinline__ void ldsm_x4_t(unsigned addr, unsigned& r0, unsigned& r1,
                                          unsigned& r2, unsigned& r3) {
    asm volatile("ldmatrix.sync.aligned.m8n8.x4.trans.shared.b16 {%0,%1,%2,%3}, [%4];"
                 : "=r"(r0), "=r"(r1), "=r"(r2), "=r"(r3) : "r"(addr));
}

__device__ __forceinline__ void mma_bf16(float* c, unsigned a0, unsigned a1, unsigned a2,
                                         unsigned a3, unsigned b0, unsigned b1) {
    asm volatile(
        "mma.sync.aligned.m16n8k16.row.col.f32.bf16.bf16.f32 "
        "{%0,%1,%2,%3}, {%4,%5,%6,%7}, {%8,%9}, {%0,%1,%2,%3};"
        : "+f"(c[0]), "+f"(c[1]), "+f"(c[2]), "+f"(c[3])
        : "r"(a0), "r"(a1), "r"(a2), "r"(a3), "r"(b0), "r"(b1));
}

__device__ __forceinline__ float escore(float s) {
    // exp(leaky_relu(s, 0.2)); scores bounded ~[-10,10] so no stabilization needed
    float l = fmaxf(s, 0.2f * s);
    return __expf(l);
}

__device__ __forceinline__ float2 bf2_to_f2(unsigned u) {
    __nv_bfloat162 b = *reinterpret_cast<__nv_bfloat162*>(&u);
    return make_float2(__low2float(b), __high2float(b));
}

// ---------------- kernel 1: convert feature/W to bf16, zero accum ----------------
__global__ void prep_kernel(const float* __restrict__ feature, const float* __restrict__ W) {
    int i = blockIdx.x * 256 + threadIdx.x;          // 2048 blocks -> 524288 threads
    #pragma unroll
    for (int r = 0; r < 4; r++) {
        int k = i + r * 524288;                       // 4 * 524288 = NN*FF
        g_featb[k] = __float2bfloat16(feature[k]);
    }
    g_Wb[i] = __float2bfloat16(W[i]);                // HH*FF*DD == 524288
    g_accum[i] = 0.0f;                               // NN*DD   == 524288
}

// ---------------- kernel 2: adjacency -> bitmask ----------------
__global__ void pack_adj_kernel(const int* __restrict__ adj) {
    int gid = blockIdx.x * 256 + threadIdx.x;        // 65536 blocks
    int w = gid >> 5;
    int lane = gid & 31;
    unsigned mask = __ballot_sync(0xffffffffu, adj[(size_t)w * 32 + lane] > 0);
    if (lane == 0) g_adjbits[w] = mask;
}

// ---------------- kernel 3: Wh = feature @ W[h]  (bf16 HMMA) ----------------
// grid (64 row-tiles, 8 heads), 128 threads (4 warps, 16 rows each), full D=128
__global__ void __launch_bounds__(128) proj_kernel() {
    __shared__ __nv_bfloat16 sA[64][72];    // 64 rows x 64 k, pad->conflict-free LDSM
    __shared__ __nv_bfloat16 sB[64][136];   // 64 k x 128 d, pad->conflict-free LDSM

    int h = blockIdx.y;
    int rowbase = blockIdx.x * 64;
    int t = threadIdx.x;
    int warp = t >> 5, lane = t & 31;
    int g = lane >> 2, tid4 = lane & 3;
    int m0 = warp * 16;
    int lr = (lane & 7) + ((lane & 8) ? 8 : 0);  // ldmatrix row within 16
    int lc = (lane & 16) ? 8 : 0;                // ldmatrix col block

    float acc[16][4];
    #pragma unroll
    for (int i = 0; i < 16; i++)
        #pragma unroll
        for (int j = 0; j < 4; j++) acc[i][j] = 0.0f;

    for (int kc = 0; kc < FF; kc += 64) {
        __syncthreads();
        // load A tile: feature[rowbase:+64][kc:+64]
        const uint4* gA = (const uint4*)(g_featb + (size_t)rowbase * FF + kc);
        #pragma unroll
        for (int r = 0; r < 4; r++) {
            int li = r * 128 + t;
            int row = li >> 3, q = li & 7;
            *(uint4*)&sA[row][q * 8] = gA[row * (FF / 8) + q];
        }
        // load B tile: W[h][kc:+64][0:128]
        const uint4* gB = (const uint4*)(g_Wb + ((size_t)h * FF + kc) * DD);
        #pragma unroll
        for (int r = 0; r < 8; r++) {
            int li = r * 128 + t;
            int row = li >> 4, q = li & 15;
            *(uint4*)&sB[row][q * 8] = gB[row * 16 + q];
        }
        __syncthreads();

        #pragma unroll
        for (int kk = 0; kk < 64; kk += 16) {
            unsigned a0, a1, a2, a3;
            ldsm_x4(smem_u32(&sA[m0 + lr][kk + lc]), a0, a1, a2, a3);
            #pragma unroll
            for (int nb = 0; nb < 8; nb++) {
                unsigned b0, b1, b2, b3;
                ldsm_x4_t(smem_u32(&sB[kk + lr][nb * 16 + lc]), b0, b1, b2, b3);
                mma_bf16(acc[2 * nb], a0, a1, a2, a3, b0, b1);
                mma_bf16(acc[2 * nb + 1], a0, a1, a2, a3, b2, b3);
            }
        }
    }

    int row_lo = rowbase + m0 + g;
    int row_hi = row_lo + 8;
    __nv_bfloat16* outlo = g_Whb + ((size_t)h * NN + row_lo) * DD;
    __nv_bfloat16* outhi = g_Whb + ((size_t)h * NN + row_hi) * DD;
    #pragma unroll
    for (int nb = 0; nb < 16; nb++) {
        int col = nb * 8 + 2 * tid4;
        *(unsigned*)(outlo + col) = pack_bf16x2(acc[nb][0], acc[nb][1]);
        *(unsigned*)(outhi + col) = pack_bf16x2(acc[nb][2], acc[nb][3]);
    }
}

// ---------------- kernel 4: s1/s2 = Wh . a1/a2 ----------------
__global__ void s12_kernel(const float* __restrict__ a1, const float* __restrict__ a2) {
    int gw = (blockIdx.x * blockDim.x + threadIdx.x) >> 5;  // 32768 warps
    int lane = threadIdx.x & 31;
    int h = gw >> 12;
    int n = gw & (NN - 1);
    const unsigned* wp = (const unsigned*)(g_Whb + ((size_t)h * NN + n) * DD + lane * 4);
    float2 w01 = bf2_to_f2(wp[0]);
    float2 w23 = bf2_to_f2(wp[1]);
    float4 v1 = *(const float4*)(a1 + h * DD + lane * 4);
    float4 v2 = *(const float4*)(a2 + h * DD + lane * 4);
    float d1 = w01.x * v1.x + w01.y * v1.y + w23.x * v1.z + w23.y * v1.w;
    float d2 = w01.x * v2.x + w01.y * v2.y + w23.x * v2.z + w23.y * v2.w;
    #pragma unroll
    for (int o = 16; o; o >>= 1) {
        d1 += __shfl_xor_sync(0xffffffffu, d1, o);
        d2 += __shfl_xor_sync(0xffffffffu, d2, o);
    }
    if (lane == 0) {
        g_s1[gw] = d1;
        g_s2[gw] = d2;
    }
}

// ---------------- kernel 5: fused masked-softmax aggregation ----------------
// h'[h,i,:] = (1/Z_i) * sum_j adj(i,j) * exp(lrelu(s1_i+s2_j)) * Wh[h,j,:]
// P is generated in registers directly in mma A-fragment layout. Z folded in.
// grid (64 row-tiles, 8 heads), 128 threads (4 warps x 16 rows), D=128 per CTA.
__global__ void __launch_bounds__(128) attn_kernel() {
    __shared__ __nv_bfloat16 sB[64][136];   // Wh[j-tile][d], padded
    __shared__ float sS2[64];

    int h = blockIdx.y;
    int rowbase = blockIdx.x * 64;
    int t = threadIdx.x;
    int warp = t >> 5, lane = t & 31;
    int g = lane >> 2, tid4 = lane & 3;
    int m0 = warp * 16;
    int lr = (lane & 7) + ((lane & 8) ? 8 : 0);
    int lc = (lane & 16) ? 8 : 0;

    int row_lo = rowbase + m0 + g;
    int row_hi = row_lo + 8;
    float s1_lo = g_s1[h * NN + row_lo];
    float s1_hi = g_s1[h * NN + row_hi];
    const uint2* bits_lo = (const uint2*)&g_adjbits[(size_t)row_lo * (NN / 32)];
    const uint2* bits_hi = (const uint2*)&g_adjbits[(size_t)row_hi * (NN / 32)];

    float acc[16][4];
    #pragma unroll
    for (int i = 0; i < 16; i++)
        #pragma unroll
        for (int j = 0; j < 4; j++) acc[i][j] = 0.0f;
    float z_lo = 0.0f, z_hi = 0.0f;

    for (int kc = 0; kc < NN; kc += 64) {
        __syncthreads();
        const uint4* gB = (const uint4*)(g_Whb + ((size_t)h * NN + kc) * DD);
        #pragma unroll
        for (int r = 0; r < 8; r++) {
            int li = r * 128 + t;
            int row = li >> 4, q = li & 15;
            *(uint4*)&sB[row][q * 8] = gB[row * 16 + q];
        }
        if (t < 64) sS2[t] = g_s2[h * NN + kc + t];
        uint2 wl = bits_lo[kc >> 6];
        uint2 wh = bits_hi[kc >> 6];
        unsigned long long BL = (unsigned long long)wl.x | ((unsigned long long)wl.y << 32);
        unsigned long long BH = (unsigned long long)wh.x | ((unsigned long long)wh.y << 32);
        __syncthreads();

        #pragma unroll
        for (int kk = 0; kk < 64; kk += 16) {
            int c0 = kk + 2 * tid4;
            float s2a = sS2[c0], s2b = sS2[c0 + 1];
            float s2c = sS2[c0 + 8], s2d = sS2[c0 + 9];

            float e00 = escore(s1_lo + s2a), e01 = escore(s1_lo + s2b);
            float e02 = escore(s1_lo + s2c), e03 = escore(s1_lo + s2d);
            float e10 = escore(s1_hi + s2a), e11 = escore(s1_hi + s2b);
            float e12 = escore(s1_hi + s2c), e13 = escore(s1_hi + s2d);

            unsigned ml = (unsigned)(BL >> c0);
            unsigned mh = (unsigned)(BH >> c0);
            float p00 = (ml & 1u)   ? e00 : 0.0f;
            float p01 = (ml & 2u)   ? e01 : 0.0f;
            float p02 = (ml & 256u) ? e02 : 0.0f;
            float p03 = (ml & 512u) ? e03 : 0.0f;
            float p10 = (mh & 1u)   ? e10 : 0.0f;
            float p11 = (mh & 2u)   ? e11 : 0.0f;
            float p12 = (mh & 256u) ? e12 : 0.0f;
            float p13 = (mh & 512u) ? e13 : 0.0f;

            z_lo += (p00 + p01) + (p02 + p03);
            z_hi += (p10 + p11) + (p12 + p13);

            unsigned a0 = pack_bf16x2(p00, p01);
            unsigned a1 = pack_bf16x2(p10, p11);
            unsigned a2 = pack_bf16x2(p02, p03);
            unsigned a3 = pack_bf16x2(p12, p13);

            #pragma unroll
            for (int nb = 0; nb < 8; nb++) {
                unsigned b0, b1, b2, b3;
                ldsm_x4_t(smem_u32(&sB[kk + lr][nb * 16 + lc]), b0, b1, b2, b3);
                mma_bf16(acc[2 * nb], a0, a1, a2, a3, b0, b1);
                mma_bf16(acc[2 * nb + 1], a0, a1, a2, a3, b2, b3);
            }
        }
    }

    // Z lives replicated across the 4 threads of each quad (each holds 1/4 of cols)
    z_lo += __shfl_xor_sync(0xffffffffu, z_lo, 1);
    z_lo += __shfl_xor_sync(0xffffffffu, z_lo, 2);
    z_hi += __shfl_xor_sync(0xffffffffu, z_hi, 1);
    z_hi += __shfl_xor_sync(0xffffffffu, z_hi, 2);
    float inv_lo = 1.0f / z_lo;
    float inv_hi = 1.0f / z_hi;

    float* out_lo = g_accum + (size_t)row_lo * DD;
    float* out_hi = g_accum + (size_t)row_hi * DD;
    #pragma unroll
    for (int nb = 0; nb < 16; nb++) {
        int col = nb * 8 + 2 * tid4;
        float v0 = acc[nb][0] * inv_lo;
        float v1 = acc[nb][1] * inv_lo;
        float v2 = acc[nb][2] * inv_hi;
        float v3 = acc[nb][3] * inv_hi;
        v0 = (v0 > 0.0f) ? v0 : (__expf(v0) - 1.0f);   // elu
        v1 = (v1 > 0.0f) ? v1 : (__expf(v1) - 1.0f);
        v2 = (v2 > 0.0f) ? v2 : (__expf(v2) - 1.0f);
        v3 = (v3 > 0.0f) ? v3 : (__expf(v3) - 1.0f);
        atomicAdd(out_lo + col, v0);
        atomicAdd(out_lo + col + 1, v1);
        atomicAdd(out_hi + col, v2);
        atomicAdd(out_hi + col + 1, v3);
    }
}

// ---------------- kernel 6: head-mean -> log_softmax -> mean ----------------
__global__ void final_kernel(float* __restrict__ out) {
    int warp = threadIdx.x >> 5;
    int lane = threadIdx.x & 31;
    int row = blockIdx.x * 8 + warp;               // 512 blocks -> 4096 rows
    float4 v = *(const float4*)(g_accum + (size_t)row * DD + lane * 4);
    float x0 = v.x * 0.125f, x1 = v.y * 0.125f;    // /H (head mean)
    float x2 = v.z * 0.125f, x3 = v.w * 0.125f;
    float mx = fmaxf(fmaxf(x0, x1), fmaxf(x2, x3));
    #pragma unroll
    for (int o = 16; o; o >>= 1) mx = fmaxf(mx, __shfl_xor_sync(0xffffffffu, mx, o));
    float se = __expf(x0 - mx) + __expf(x1 - mx) + __expf(x2 - mx) + __expf(x3 - mx);
    float sx = x0 + x1 + x2 + x3;
    #pragma unroll
    for (int o = 16; o; o >>= 1) {
        se += __shfl_xor_sync(0xffffffffu, se, o);
        sx += __shfl_xor_sync(0xffffffffu, sx, o);
    }
    if (lane == 0) out[row] = sx * (1.0f / 128.0f) - mx - logf(se);
}

// ---------------- launch ----------------
extern "C" void kernel_launch(void* const* d_in, const int* in_sizes, int n_in,
                              void* d_out, int out_size) {
    const float* feature = (const float*)d_in[0];
    const int* adj = (const int*)d_in[1];
    const float* W = (const float*)d_in[2];
    const float* a1 = (const float*)d_in[3];
    const float* a2 = (const float*)d_in[4];
    float* out = (float*)d_out;

    prep_kernel<<<2048, 256>>>(feature, W);
    pack_adj_kernel<<<65536, 256>>>(adj);
    proj_kernel<<<dim3(64, 8), 128>>>();
    s12_kernel<<<4096, 256>>>(a1, a2);
    attn_kernel<<<dim3(64, 8), 128>>>();
    final_kernel<<<512, 256>>>(out);
}

// round 3
// speedup vs baseline: 1.2036x; 1.2036x over previous
#include <cuda_runtime.h>
#include <cuda_bf16.h>
#include <cstdint>

#define NN 4096
#define FF 512
#define DD 128
#define HH 8

// ---------------- scratch (static device globals; no allocs) ----------------
__device__ __nv_bfloat16 g_featb[NN * FF];          // 4 MB
__device__ __nv_bfloat16 g_Wb[HH * FF * DD];        // 1 MB
__device__ __nv_bfloat16 g_Whb[HH * NN * DD];       // 8 MB
__device__ float g_e1p[HH * NN];                    // exp(s1)
__device__ float g_e1n[HH * NN];                    // exp(0.2 s1)
__device__ float g_e2p[HH * NN];                    // exp(s2)
__device__ float g_e2n[HH * NN];                    // exp(0.2 s2)
__device__ unsigned g_adjbits[NN * (NN / 32)];      // 2 MB
__device__ float g_accum[NN * DD];                  // 2 MB

// ---------------- helpers ----------------
__device__ __forceinline__ unsigned pack_bf16x2(float lo, float hi) {
    unsigned r;
    asm("cvt.rn.bf16x2.f32 %0, %1, %2;" : "=r"(r) : "f"(hi), "f"(lo));
    return r;
}
__device__ __forceinline__ unsigned smem_u32(const void* p) {
    return (unsigned)__cvta_generic_to_shared(p);
}
__device__ __forceinline__ void ldsm_x4(unsigned addr, unsigned& r0, unsigned& r1,
                                        unsigned& r2, unsigned& r3) {
    asm volatile("ldmatrix.sync.aligned.m8n8.x4.shared.b16 {%0,%1,%2,%3}, [%4];"
                 : "=r"(r0), "=r"(r1), "=r"(r2), "=r"(r3) : "r"(addr));
}
__device__ __forceinline__ void ldsm_x4_t(unsigned addr, unsigned& r0, unsigned& r1,
                                          unsigned& r2, unsigned& r3) {
    asm volatile("ldmatrix.sync.aligned.m8n8.x4.trans.shared.b16 {%0,%1,%2,%3}, [%4];"
                 : "=r"(r0), "=r"(r1), "=r"(r2), "=r"(r3) : "r"(addr));
}
__device__ __forceinline__ void mma_bf16(float* c, unsigned a0, unsigned a1, unsigned a2,
                                         unsigned a3, unsigned b0, unsigned b1) {
    asm volatile(
        "mma.sync.aligned.m16n8k16.row.col.f32.bf16.bf16.f32 "
        "{%0,%1,%2,%3}, {%4,%5,%6,%7}, {%8,%9}, {%0,%1,%2,%3};"
        : "+f"(c[0]), "+f"(c[1]), "+f"(c[2]), "+f"(c[3])
        : "r"(a0), "r"(a1), "r"(a2), "r"(a3), "r"(b0), "r"(b1));
}
#define CP_ASYNC16(dst, src) \
    asm volatile("cp.async.cg.shared.global [%0], [%1], 16;" :: "r"(dst), "l"(src))
#define CP_ASYNC4(dst, src) \
    asm volatile("cp.async.ca.shared.global [%0], [%1], 4;" :: "r"(dst), "l"(src))
#define CP_COMMIT asm volatile("cp.async.commit_group;")
#define CP_WAIT1 asm volatile("cp.async.wait_group 1;")
#define CP_WAIT0 asm volatile("cp.async.wait_group 0;")

// ---------------- kernel 1: convert feature/W to bf16, zero accum ----------------
__global__ void prep_kernel(const float* __restrict__ feature, const float* __restrict__ W) {
    int i = blockIdx.x * 256 + threadIdx.x;          // 2048 blocks -> 524288 threads
    #pragma unroll
    for (int r = 0; r < 4; r++) {
        int k = i + r * 524288;                       // 4 * 524288 = NN*FF
        g_featb[k] = __float2bfloat16(feature[k]);
    }
    g_Wb[i] = __float2bfloat16(W[i]);                // HH*FF*DD == 524288
    g_accum[i] = 0.0f;                               // NN*DD   == 524288
}

// ---------------- kernel 2: adjacency -> bitmask ----------------
__global__ void pack_adj_kernel(const int* __restrict__ adj) {
    int gid = blockIdx.x * 256 + threadIdx.x;        // 65536 blocks
    int w = gid >> 5;
    int lane = gid & 31;
    unsigned mask = __ballot_sync(0xffffffffu, adj[(size_t)w * 32 + lane] > 0);
    if (lane == 0) g_adjbits[w] = mask;
}

// ---------------- kernel 3: Wh = feature @ W[h]; epilogue makes exp(s1/s2) ----------------
// grid (32 row-tiles, 8 heads), 256 threads (8 warps x 16 rows), full D=128
__global__ void __launch_bounds__(256, 2) proj_kernel(const float* __restrict__ a1,
                                                      const float* __restrict__ a2) {
    __shared__ __nv_bfloat16 sA[128][72];   // 128 rows x 64 k, padded
    __shared__ __nv_bfloat16 sB[64][136];   // 64 k x 128 d, padded
    __shared__ float sA1[128], sA2[128];

    int h = blockIdx.y;
    int rowbase = blockIdx.x * 128;
    int t = threadIdx.x;
    int warp = t >> 5, lane = t & 31;
    int g = lane >> 2, tid4 = lane & 3;
    int m0 = warp * 16;
    int lr = (lane & 7) + ((lane & 8) ? 8 : 0);
    int lc = (lane & 16) ? 8 : 0;

    if (t < 128) sA1[t] = a1[h * DD + t];
    else sA2[t - 128] = a2[h * DD + (t - 128)];

    float acc[16][4];
    #pragma unroll
    for (int i = 0; i < 16; i++)
        #pragma unroll
        for (int j = 0; j < 4; j++) acc[i][j] = 0.0f;

    for (int kc = 0; kc < FF; kc += 64) {
        __syncthreads();
        const uint4* gA = (const uint4*)(g_featb + (size_t)rowbase * FF + kc);
        #pragma unroll
        for (int r = 0; r < 4; r++) {
            int li = r * 256 + t;                    // 1024 chunks: 128 rows x 8
            int row = li >> 3, q = li & 7;
            *(uint4*)&sA[row][q * 8] = gA[row * (FF / 8) + q];
        }
        const uint4* gB = (const uint4*)(g_Wb + ((size_t)h * FF + kc) * DD);
        #pragma unroll
        for (int r = 0; r < 4; r++) {
            int li = r * 256 + t;                    // 1024 chunks: 64 rows x 16
            int row = li >> 4, q = li & 15;
            *(uint4*)&sB[row][q * 8] = gB[row * 16 + q];
        }
        __syncthreads();

        #pragma unroll
        for (int kk = 0; kk < 64; kk += 16) {
            unsigned a0, a1r, a2r, a3;
            ldsm_x4(smem_u32(&sA[m0 + lr][kk + lc]), a0, a1r, a2r, a3);
            #pragma unroll
            for (int nb = 0; nb < 8; nb++) {
                unsigned b0, b1, b2, b3;
                ldsm_x4_t(smem_u32(&sB[kk + lr][nb * 16 + lc]), b0, b1, b2, b3);
                mma_bf16(acc[2 * nb], a0, a1r, a2r, a3, b0, b1);
                mma_bf16(acc[2 * nb + 1], a0, a1r, a2r, a3, b2, b3);
            }
        }
    }

    int row_lo = rowbase + m0 + g;
    int row_hi = row_lo + 8;

    // write Wh (bf16)
    __nv_bfloat16* outlo = g_Whb + ((size_t)h * NN + row_lo) * DD;
    __nv_bfloat16* outhi = g_Whb + ((size_t)h * NN + row_hi) * DD;
    #pragma unroll
    for (int i = 0; i < 16; i++) {
        int col = i * 8 + 2 * tid4;
        *(unsigned*)(outlo + col) = pack_bf16x2(acc[i][0], acc[i][1]);
        *(unsigned*)(outhi + col) = pack_bf16x2(acc[i][2], acc[i][3]);
    }

    // fused s1/s2 dot products from fp32 accumulators
    float d1lo = 0, d2lo = 0, d1hi = 0, d2hi = 0;
    #pragma unroll
    for (int i = 0; i < 16; i++) {
        int col = i * 8 + 2 * tid4;
        float v1a = sA1[col], v1b = sA1[col + 1];
        float v2a = sA2[col], v2b = sA2[col + 1];
        d1lo += acc[i][0] * v1a + acc[i][1] * v1b;
        d1hi += acc[i][2] * v1a + acc[i][3] * v1b;
        d2lo += acc[i][0] * v2a + acc[i][1] * v2b;
        d2hi += acc[i][2] * v2a + acc[i][3] * v2b;
    }
    #pragma unroll
    for (int o = 1; o <= 2; o <<= 1) {
        d1lo += __shfl_xor_sync(0xffffffffu, d1lo, o);
        d1hi += __shfl_xor_sync(0xffffffffu, d1hi, o);
        d2lo += __shfl_xor_sync(0xffffffffu, d2lo, o);
        d2hi += __shfl_xor_sync(0xffffffffu, d2hi, o);
    }
    if (tid4 == 0) {
        int ilo = h * NN + row_lo, ihi = h * NN + row_hi;
        g_e1p[ilo] = __expf(d1lo);        g_e1p[ihi] = __expf(d1hi);
        g_e1n[ilo] = __expf(0.2f * d1lo); g_e1n[ihi] = __expf(0.2f * d1hi);
        g_e2p[ilo] = __expf(d2lo);        g_e2p[ihi] = __expf(d2hi);
        g_e2n[ilo] = __expf(0.2f * d2lo); g_e2n[ihi] = __expf(0.2f * d2hi);
    }
}

// ---------------- kernel 4: fused masked-softmax aggregation ----------------
// p_ij = max(E1p_i*E2p_j, E1n_i*E2n_j) masked; Z folded; no MUFU in hot loop.
// grid (32 row-tiles, 8 heads), 256 threads (8 warps x 16 rows), D=128.
__global__ void __launch_bounds__(256, 2) attn_kernel() {
    __shared__ __nv_bfloat16 sB[2][64][136];   // double-buffered Wh tile
    __shared__ float sE2p[2][64], sE2n[2][64];

    int h = blockIdx.y;
    int rowbase = blockIdx.x * 128;
    int t = threadIdx.x;
    int warp = t >> 5, lane = t & 31;
    int g = lane >> 2, tid4 = lane & 3;
    int m0 = warp * 16;
    int lr = (lane & 7) + ((lane & 8) ? 8 : 0);
    int lc = (lane & 16) ? 8 : 0;

    int row_lo = rowbase + m0 + g;
    int row_hi = row_lo + 8;
    float e1p_lo = g_e1p[h * NN + row_lo];
    float e1p_hi = g_e1p[h * NN + row_hi];
    float e1n_lo = g_e1n[h * NN + row_lo];
    float e1n_hi = g_e1n[h * NN + row_hi];
    const uint2* bits_lo = (const uint2*)&g_adjbits[(size_t)row_lo * (NN / 32)];
    const uint2* bits_hi = (const uint2*)&g_adjbits[(size_t)row_hi * (NN / 32)];

    float acc[16][4];
    #pragma unroll
    for (int i = 0; i < 16; i++)
        #pragma unroll
        for (int j = 0; j < 4; j++) acc[i][j] = 0.0f;
    float z_lo = 0.0f, z_hi = 0.0f;

    // ---- prefetch tile 0 ----
    {
        const __nv_bfloat16* src = g_Whb + (size_t)h * NN * DD;
        #pragma unroll
        for (int r = 0; r < 4; r++) {
            int li = r * 256 + t;
            int row = li >> 4, q = li & 15;
            CP_ASYNC16(smem_u32(&sB[0][row][q * 8]), src + row * DD + q * 8);
        }
        if (t < 64) CP_ASYNC4(smem_u32(&sE2p[0][t]), &g_e2p[h * NN + t]);
        else if (t < 128) CP_ASYNC4(smem_u32(&sE2n[0][t - 64]), &g_e2n[h * NN + (t - 64)]);
    }
    CP_COMMIT;
    uint2 wl_cur = bits_lo[0];
    uint2 wh_cur = bits_hi[0];

    for (int it = 0; it < NN / 64; it++) {
        int nxt = it + 1;
        uint2 wl_nxt = make_uint2(0, 0), wh_nxt = make_uint2(0, 0);
        if (nxt < NN / 64) {
            int kc = nxt * 64;
            const __nv_bfloat16* src = g_Whb + ((size_t)h * NN + kc) * DD;
            int b = nxt & 1;
            #pragma unroll
            for (int r = 0; r < 4; r++) {
                int li = r * 256 + t;
                int row = li >> 4, q = li & 15;
                CP_ASYNC16(smem_u32(&sB[b][row][q * 8]), src + row * DD + q * 8);
            }
            if (t < 64) CP_ASYNC4(smem_u32(&sE2p[b][t]), &g_e2p[h * NN + kc + t]);
            else if (t < 128) CP_ASYNC4(smem_u32(&sE2n[b][t - 64]), &g_e2n[h * NN + kc + (t - 64)]);
            wl_nxt = bits_lo[nxt];
            wh_nxt = bits_hi[nxt];
        }
        CP_COMMIT;
        if (nxt < NN / 64) { CP_WAIT1; } else { CP_WAIT0; }
        __syncthreads();

        int b = it & 1;
        unsigned long long BL = (unsigned long long)wl_cur.x | ((unsigned long long)wl_cur.y << 32);
        unsigned long long BH = (unsigned long long)wh_cur.x | ((unsigned long long)wh_cur.y << 32);

        #pragma unroll
        for (int kk = 0; kk < 64; kk += 16) {
            int c0 = kk + 2 * tid4;
            float2 ep_a = *(const float2*)&sE2p[b][c0];
            float2 ep_b = *(const float2*)&sE2p[b][c0 + 8];
            float2 en_a = *(const float2*)&sE2n[b][c0];
            float2 en_b = *(const float2*)&sE2n[b][c0 + 8];

            float p00 = fmaxf(e1p_lo * ep_a.x, e1n_lo * en_a.x);
            float p01 = fmaxf(e1p_lo * ep_a.y, e1n_lo * en_a.y);
            float p02 = fmaxf(e1p_lo * ep_b.x, e1n_lo * en_b.x);
            float p03 = fmaxf(e1p_lo * ep_b.y, e1n_lo * en_b.y);
            float p10 = fmaxf(e1p_hi * ep_a.x, e1n_hi * en_a.x);
            float p11 = fmaxf(e1p_hi * ep_a.y, e1n_hi * en_a.y);
            float p12 = fmaxf(e1p_hi * ep_b.x, e1n_hi * en_b.x);
            float p13 = fmaxf(e1p_hi * ep_b.y, e1n_hi * en_b.y);

            unsigned ml = (unsigned)(BL >> c0);
            unsigned mh = (unsigned)(BH >> c0);
            p00 = (ml & 1u)   ? p00 : 0.0f;
            p01 = (ml & 2u)   ? p01 : 0.0f;
            p02 = (ml & 256u) ? p02 : 0.0f;
            p03 = (ml & 512u) ? p03 : 0.0f;
            p10 = (mh & 1u)   ? p10 : 0.0f;
            p11 = (mh & 2u)   ? p11 : 0.0f;
            p12 = (mh & 256u) ? p12 : 0.0f;
            p13 = (mh & 512u) ? p13 : 0.0f;

            z_lo += (p00 + p01) + (p02 + p03);
            z_hi += (p10 + p11) + (p12 + p13);

            unsigned a0 = pack_bf16x2(p00, p01);
            unsigned a1 = pack_bf16x2(p10, p11);
            unsigned a2 = pack_bf16x2(p02, p03);
            unsigned a3 = pack_bf16x2(p12, p13);

            #pragma unroll
            for (int nb = 0; nb < 8; nb++) {
                unsigned b0, b1, b2, b3;
                ldsm_x4_t(smem_u32(&sB[b][kk + lr][nb * 16 + lc]), b0, b1, b2, b3);
                mma_bf16(acc[2 * nb], a0, a1, a2, a3, b0, b1);
                mma_bf16(acc[2 * nb + 1], a0, a1, a2, a3, b2, b3);
            }
        }
        __syncthreads();
        wl_cur = wl_nxt;
        wh_cur = wh_nxt;
    }

    // quad-reduce Z (cols partitioned over tid4)
    z_lo += __shfl_xor_sync(0xffffffffu, z_lo, 1);
    z_lo += __shfl_xor_sync(0xffffffffu, z_lo, 2);
    z_hi += __shfl_xor_sync(0xffffffffu, z_hi, 1);
    z_hi += __shfl_xor_sync(0xffffffffu, z_hi, 2);
    float inv_lo = 1.0f / z_lo;
    float inv_hi = 1.0f / z_hi;

    float* out_lo = g_accum + (size_t)row_lo * DD;
    float* out_hi = g_accum + (size_t)row_hi * DD;
    #pragma unroll
    for (int i = 0; i < 16; i++) {
        int col = i * 8 + 2 * tid4;
        float v0 = acc[i][0] * inv_lo;
        float v1 = acc[i][1] * inv_lo;
        float v2 = acc[i][2] * inv_hi;
        float v3 = acc[i][3] * inv_hi;
        v0 = (v0 > 0.0f) ? v0 : (__expf(v0) - 1.0f);   // elu
        v1 = (v1 > 0.0f) ? v1 : (__expf(v1) - 1.0f);
        v2 = (v2 > 0.0f) ? v2 : (__expf(v2) - 1.0f);
        v3 = (v3 > 0.0f) ? v3 : (__expf(v3) - 1.0f);
        atomicAdd(out_lo + col, v0);
        atomicAdd(out_lo + col + 1, v1);
        atomicAdd(out_hi + col, v2);
        atomicAdd(out_hi + col + 1, v3);
    }
}

// ---------------- kernel 5: head-mean -> log_softmax -> mean ----------------
__global__ void final_kernel(float* __restrict__ out) {
    int warp = threadIdx.x >> 5;
    int lane = threadIdx.x & 31;
    int row = blockIdx.x * 8 + warp;               // 512 blocks -> 4096 rows
    float4 v = *(const float4*)(g_accum + (size_t)row * DD + lane * 4);
    float x0 = v.x * 0.125f, x1 = v.y * 0.125f;    // /H (head mean)
    float x2 = v.z * 0.125f, x3 = v.w * 0.125f;
    float mx = fmaxf(fmaxf(x0, x1), fmaxf(x2, x3));
    #pragma unroll
    for (int o = 16; o; o >>= 1) mx = fmaxf(mx, __shfl_xor_sync(0xffffffffu, mx, o));
    float se = __expf(x0 - mx) + __expf(x1 - mx) + __expf(x2 - mx) + __expf(x3 - mx);
    float sx = x0 + x1 + x2 + x3;
    #pragma unroll
    for (int o = 16; o; o >>= 1) {
        se += __shfl_xor_sync(0xffffffffu, se, o);
        sx += __shfl_xor_sync(0xffffffffu, sx, o);
    }
    if (lane == 0) out[row] = sx * (1.0f / 128.0f) - mx - logf(se);
}

// ---------------- launch ----------------
extern "C" void kernel_launch(void* const* d_in, const int* in_sizes, int n_in,
                              void* d_out, int out_size) {
    const float* feature = (const float*)d_in[0];
    const int* adj = (const int*)d_in[1];
    const float* W = (const float*)d_in[2];
    const float* a1 = (const float*)d_in[3];
    const float* a2 = (const float*)d_in[4];
    float* out = (float*)d_out;

    prep_kernel<<<2048, 256>>>(feature, W);
    pack_adj_kernel<<<65536, 256>>>(adj);
    proj_kernel<<<dim3(32, 8), 256>>>(a1, a2);
    attn_kernel<<<dim3(32, 8), 256>>>();
    final_kernel<<<512, 256>>>(out);
}